// round 1
// baseline (speedup 1.0000x reference)
#include <cuda_runtime.h>

// ---------------------------------------------------------------------------
// EdgeNetwork: out[e] = MLP(x[start_e], x[end_e], vp[batch[start_e]])
// Strategy:
//   Kernel 0: detect whether index tensors are int64 or int32 (device flag).
//   Kernel 1: per-node precompute  xs[n] = x[n]@W1[0:16]  + b1 + vp[batch[n]]@W1[32:48]
//                                  xb[n] = x[n]@W1[16:32]
//   Kernel 2: per-edge: h = xs[start]+xb[end]; 3x (LayerNorm+tanh) with H=8
//             fully in registers; weights in shared.
// ---------------------------------------------------------------------------

#define NODE_CAP 131072

__device__ __align__(16) float g_xs[NODE_CAP * 8];
__device__ __align__(16) float g_xb[NODE_CAP * 8];
__device__ int g_flag;  // 1 => indices are int64, 0 => int32

// ---------------------------------------------------------------------------
// Dtype detection: edge_index holds random values in [0, N). If stored as
// int64 (little-endian), every odd 32-bit word is a zero high-half. If int32,
// odd words are random nonzero values (P[all zero] ~ 0).
// ---------------------------------------------------------------------------
__global__ void detect_k(const int* __restrict__ ei, int n_elems) {
    if (threadIdx.x != 0 || blockIdx.x != 0) return;
    int lim = n_elems < 256 ? n_elems : 256;  // safe under either dtype
    int nz = 0;
    for (int i = 1; i < lim; i += 2) nz |= ei[i];
    g_flag = (nz == 0) ? 1 : 0;
}

// ---------------------------------------------------------------------------
// Per-node precompute
// ---------------------------------------------------------------------------
__global__ void __launch_bounds__(256) pre_k(
    const float* __restrict__ x, const int* __restrict__ batch_raw,
    const float* __restrict__ vp, const float* __restrict__ W1,
    const float* __restrict__ b1, int N, int G)
{
    __shared__ float sW1[48 * 8];
    __shared__ float svp[64 * 16];
    __shared__ float sb1[8];
    int t = threadIdx.x;
    for (int i = t; i < 384; i += blockDim.x) sW1[i] = W1[i];
    int gv = G * 16; if (gv > 1024) gv = 1024;
    for (int i = t; i < gv; i += blockDim.x) svp[i] = vp[i];
    if (t < 8) sb1[t] = b1[t];
    __syncthreads();

    int n = blockIdx.x * blockDim.x + t;
    if (n >= N) return;

    int is64 = g_flag;
    int g = is64 ? batch_raw[2 * n] : batch_raw[n];

    float xi[16];
    const float* xr = x + (size_t)n * 16;
#pragma unroll
    for (int k = 0; k < 16; k += 4) {
        float4 v = *(const float4*)(xr + k);
        xi[k] = v.x; xi[k + 1] = v.y; xi[k + 2] = v.z; xi[k + 3] = v.w;
    }
    const float* vg = svp + g * 16;

    float xs[8], xb[8];
#pragma unroll
    for (int j = 0; j < 8; j++) {
        float a = sb1[j];
        float b = 0.0f;
#pragma unroll
        for (int k = 0; k < 16; k++) {
            a = fmaf(xi[k], sW1[k * 8 + j], a);            // x @ W1a
            a = fmaf(vg[k], sW1[(32 + k) * 8 + j], a);     // vp @ W1c
            b = fmaf(xi[k], sW1[(16 + k) * 8 + j], b);     // x @ W1b
        }
        xs[j] = a; xb[j] = b;
    }
    float4* o1 = (float4*)(g_xs + (size_t)n * 8);
    o1[0] = make_float4(xs[0], xs[1], xs[2], xs[3]);
    o1[1] = make_float4(xs[4], xs[5], xs[6], xs[7]);
    float4* o2 = (float4*)(g_xb + (size_t)n * 8);
    o2[0] = make_float4(xb[0], xb[1], xb[2], xb[3]);
    o2[1] = make_float4(xb[4], xb[5], xb[6], xb[7]);
}

// ---------------------------------------------------------------------------
// Edge kernel helpers
// ---------------------------------------------------------------------------
__device__ __forceinline__ float fast_tanh(float z) {
    // exact identity; __expf -> MUFU.EX2, __fdividef -> MUFU.RCP. |z| <= ~2.7
    // after LayerNorm over 8 elems, so no overflow concerns (clamp for safety).
    z = fminf(fmaxf(z, -15.0f), 15.0f);
    float e = __expf(2.0f * z);
    return __fdividef(e - 1.0f, e + 1.0f);
}

__device__ __forceinline__ void ln_tanh(float h[8], const float* __restrict__ g,
                                        const float* __restrict__ be) {
    float mu = 0.0f;
#pragma unroll
    for (int j = 0; j < 8; j++) mu += h[j];
    mu *= 0.125f;
    float var = 0.0f;
#pragma unroll
    for (int j = 0; j < 8; j++) { float d = h[j] - mu; var = fmaf(d, d, var); }
    var *= 0.125f;
    float r = rsqrtf(var + 1e-5f);
#pragma unroll
    for (int j = 0; j < 8; j++) {
        float z = fmaf((h[j] - mu) * r, g[j], be[j]);
        h[j] = fast_tanh(z);
    }
}

__global__ void __launch_bounds__(256) edge_k(
    const int* __restrict__ ei, int E,
    const float* __restrict__ g1, const float* __restrict__ be1,
    const float* __restrict__ W2, const float* __restrict__ b2,
    const float* __restrict__ g2, const float* __restrict__ be2,
    const float* __restrict__ W3, const float* __restrict__ b3,
    const float* __restrict__ g3, const float* __restrict__ be3,
    const float* __restrict__ W4, const float* __restrict__ b4,
    float* __restrict__ out)
{
    __shared__ float sW2[64], sW3[64], sW4[8];
    __shared__ float sv[64];  // g1,be1,b2,g2,be2,b3,g3,be3 (8 each)
    __shared__ float sb4;
    int t = threadIdx.x;
    if (t < 64) { sW2[t] = W2[t]; sW3[t] = W3[t]; }
    if (t < 8) {
        sW4[t] = W4[t];
        sv[t]      = g1[t];  sv[8 + t]  = be1[t];
        sv[16 + t] = b2[t];  sv[24 + t] = g2[t];  sv[32 + t] = be2[t];
        sv[40 + t] = b3[t];  sv[48 + t] = g3[t];  sv[56 + t] = be3[t];
    }
    if (t == 0) sb4 = b4[0];
    __syncthreads();

    const float* sg1 = sv;       const float* sbe1 = sv + 8;
    const float* sb2 = sv + 16;  const float* sg2  = sv + 24; const float* sbe2 = sv + 32;
    const float* sb3 = sv + 40;  const float* sg3  = sv + 48; const float* sbe3 = sv + 56;

    int is64 = g_flag;
    int stride = gridDim.x * blockDim.x;
    for (int e = blockIdx.x * blockDim.x + t; e < E; e += stride) {
        int s, d;
        if (is64) { s = ei[2 * e]; d = ei[2 * (E + e)]; }
        else      { s = ei[e];     d = ei[E + e]; }

        const float4* ap = (const float4*)(g_xs + (size_t)s * 8);
        const float4* bp = (const float4*)(g_xb + (size_t)d * 8);
        float4 a0 = ap[0], a1 = ap[1];
        float4 c0 = bp[0], c1 = bp[1];

        float h[8] = { a0.x + c0.x, a0.y + c0.y, a0.z + c0.z, a0.w + c0.w,
                       a1.x + c1.x, a1.y + c1.y, a1.z + c1.z, a1.w + c1.w };
        ln_tanh(h, sg1, sbe1);

        float h2[8];
#pragma unroll
        for (int j = 0; j < 8; j++) {
            float a = sb2[j];
#pragma unroll
            for (int k = 0; k < 8; k++) a = fmaf(h[k], sW2[k * 8 + j], a);
            h2[j] = a;
        }
        ln_tanh(h2, sg2, sbe2);

        float h3[8];
#pragma unroll
        for (int j = 0; j < 8; j++) {
            float a = sb3[j];
#pragma unroll
            for (int k = 0; k < 8; k++) a = fmaf(h2[k], sW3[k * 8 + j], a);
            h3[j] = a;
        }
        ln_tanh(h3, sg3, sbe3);

        float o = sb4;
#pragma unroll
        for (int k = 0; k < 8; k++) o = fmaf(h3[k], sW4[k], o);
        out[e] = o;
    }
}

// ---------------------------------------------------------------------------
// Launch
// Input order (setup_inputs dict): x, edge_index, vp, batch,
//   W1, b1, g1, be1, W2, b2, g2, be2, W3, b3, g3, be3, W4, b4
// ---------------------------------------------------------------------------
extern "C" void kernel_launch(void* const* d_in, const int* in_sizes, int n_in,
                              void* d_out, int out_size)
{
    const float* x     = (const float*)d_in[0];
    const int*   ei    = (const int*)d_in[1];
    const float* vp    = (const float*)d_in[2];
    const int*   batch = (const int*)d_in[3];
    const float* W1  = (const float*)d_in[4];
    const float* b1  = (const float*)d_in[5];
    const float* g1  = (const float*)d_in[6];
    const float* be1 = (const float*)d_in[7];
    const float* W2  = (const float*)d_in[8];
    const float* b2  = (const float*)d_in[9];
    const float* g2  = (const float*)d_in[10];
    const float* be2 = (const float*)d_in[11];
    const float* W3  = (const float*)d_in[12];
    const float* b3  = (const float*)d_in[13];
    const float* g3  = (const float*)d_in[14];
    const float* be3 = (const float*)d_in[15];
    const float* W4  = (const float*)d_in[16];
    const float* b4  = (const float*)d_in[17];

    int N = in_sizes[0] / 16;
    int E = in_sizes[1] / 2;
    int G = in_sizes[2] / 16;

    detect_k<<<1, 1>>>(ei, in_sizes[1]);

    int pb = (N + 255) / 256;
    pre_k<<<pb, 256>>>(x, batch, vp, W1, b1, N, G);

    int eb = (E + 255) / 256;
    if (eb > 2368) eb = 2368;   // grid-stride cap: 16 blocks/SM worth on 148 SMs
    edge_k<<<eb, 256>>>(ei, E, g1, be1, W2, b2, g2, be2, W3, b3, g3, be3,
                        W4, b4, (float*)d_out);
}